// round 3
// baseline (speedup 1.0000x reference)
#include <cuda_runtime.h>

// CircleProjectionLayer: out = center + (x - center) * min(1, R / max(||x-center||, 1e-12))
// R = 1.0, B = 8388608 points, AoS float32 [B,3]. Pure HBM-streaming kernel.
//
// R2 changes vs R1 (43.4us kernel @ 6.07 TB/s DRAM):
//  - 8 points/thread (6 float4 per input array) -> 2x MLP per thread
//  - __ldcs/__stcs streaming hints (zero-reuse data, evict-first)

#define RADIUS_F 1.0f

__global__ __launch_bounds__(256)
void circle_proj_kernel(const float4* __restrict__ x4,
                        const float4* __restrict__ c4,
                        float4* __restrict__ o4,
                        int n_groups)   // n_groups = B/8 ; each group = 6 float4 = 8 points
{
    int i = blockIdx.x * blockDim.x + threadIdx.x;
    if (i >= n_groups) return;

    long base = 6L * i;

    float4 xr[6], cr[6];
    #pragma unroll
    for (int j = 0; j < 6; ++j) xr[j] = __ldcs(&x4[base + j]);
    #pragma unroll
    for (int j = 0; j < 6; ++j) cr[j] = __ldcs(&c4[base + j]);

    float xv[24], cv[24], ov[24];
    #pragma unroll
    for (int j = 0; j < 6; ++j) {
        xv[4*j+0] = xr[j].x; xv[4*j+1] = xr[j].y; xv[4*j+2] = xr[j].z; xv[4*j+3] = xr[j].w;
        cv[4*j+0] = cr[j].x; cv[4*j+1] = cr[j].y; cv[4*j+2] = cr[j].z; cv[4*j+3] = cr[j].w;
    }

    #pragma unroll
    for (int p = 0; p < 8; ++p) {
        float dx = xv[3*p + 0] - cv[3*p + 0];
        float dy = xv[3*p + 1] - cv[3*p + 1];
        float dz = xv[3*p + 2] - cv[3*p + 2];
        float n2 = fmaf(dx, dx, fmaf(dy, dy, dz * dz));
        // scale = min(1, R / max(n, 1e-12)) == min(1, R * rsqrt(max(n2, 1e-24)))
        float s = fminf(1.0f, RADIUS_F * rsqrtf(fmaxf(n2, 1e-24f)));
        ov[3*p + 0] = fmaf(dx, s, cv[3*p + 0]);
        ov[3*p + 1] = fmaf(dy, s, cv[3*p + 1]);
        ov[3*p + 2] = fmaf(dz, s, cv[3*p + 2]);
    }

    #pragma unroll
    for (int j = 0; j < 6; ++j) {
        __stcs(&o4[base + j], make_float4(ov[4*j+0], ov[4*j+1], ov[4*j+2], ov[4*j+3]));
    }
}

// Scalar tail kernel for any leftover points (B not divisible by 8). For the
// benched shape (B = 8388608 = 8 * 1048576) this launches 0 blocks.
__global__ void circle_proj_tail(const float* __restrict__ x,
                                 const float* __restrict__ c,
                                 float* __restrict__ o,
                                 int start_pt, int n_pt)
{
    int p = start_pt + blockIdx.x * blockDim.x + threadIdx.x;
    if (p >= n_pt) return;
    float dx = x[3*p + 0] - c[3*p + 0];
    float dy = x[3*p + 1] - c[3*p + 1];
    float dz = x[3*p + 2] - c[3*p + 2];
    float n2 = fmaf(dx, dx, fmaf(dy, dy, dz * dz));
    float s = fminf(1.0f, RADIUS_F * rsqrtf(fmaxf(n2, 1e-24f)));
    o[3*p + 0] = fmaf(dx, s, c[3*p + 0]);
    o[3*p + 1] = fmaf(dy, s, c[3*p + 1]);
    o[3*p + 2] = fmaf(dz, s, c[3*p + 2]);
}

extern "C" void kernel_launch(void* const* d_in, const int* in_sizes, int n_in,
                              void* d_out, int out_size)
{
    const float* x = (const float*)d_in[0];
    const float* c = (const float*)d_in[1];
    float* o = (float*)d_out;

    int total_floats = in_sizes[0];      // B * 3
    int n_pts = total_floats / 3;
    int n_groups = n_pts / 8;            // 8 points per thread

    if (n_groups > 0) {
        int threads = 256;
        int blocks = (n_groups + threads - 1) / threads;
        circle_proj_kernel<<<blocks, threads>>>(
            (const float4*)x, (const float4*)c, (float4*)o, n_groups);
    }

    int done_pts = n_groups * 8;
    int rem = n_pts - done_pts;
    if (rem > 0) {
        circle_proj_tail<<<(rem + 255) / 256, 256>>>(x, c, o, done_pts, n_pts);
    }
}

// round 4
// speedup vs baseline: 1.0123x; 1.0123x over previous
#include <cuda_runtime.h>

// CircleProjectionLayer: out = center + (x - center) * min(1, R / max(||x-center||, 1e-12))
// R = 1.0, B = 8388608 points, AoS float32 [B,3]. HBM-streaming kernel.
//
// R3: smem-staged coalescing. All global traffic is unit-stride float4
// (every warp LDG/STG = full 128B lines); the stride-3-float AoS unpack
// happens in shared memory with a conflict-free 12-word thread stride.

#define RADIUS_F 1.0f
#define THREADS 256
#define PTS_PER_BLOCK 1024                 // 4 points/thread
#define F4_PER_BLOCK (PTS_PER_BLOCK * 3 / 4)   // 768 float4 per array per block

__global__ __launch_bounds__(THREADS)
void circle_proj_kernel(const float4* __restrict__ x4,
                        const float4* __restrict__ c4,
                        float4* __restrict__ o4)
{
    __shared__ float4 sx[F4_PER_BLOCK];
    __shared__ float4 sc[F4_PER_BLOCK];
    __shared__ float4 so[F4_PER_BLOCK];

    const int tid = threadIdx.x;
    const long blockBase = (long)blockIdx.x * F4_PER_BLOCK;

    // ---- Phase 1: fully-coalesced global -> smem (3 float4 per thread per array)
    #pragma unroll
    for (int k = 0; k < 3; ++k) {
        long g = blockBase + k * THREADS + tid;
        sx[k * THREADS + tid] = x4[g];
        sc[k * THREADS + tid] = c4[g];
    }
    __syncthreads();

    // ---- Phase 2: per-point compute. Thread t owns points [4t, 4t+4) of the
    // block = floats [12t, 12t+12) = smem float4 [3t, 3t+3). The 12-word
    // (48B) thread stride is bank-conflict-free for LDS.128/STS.128.
    {
        float4 a = sx[3 * tid + 0];
        float4 b = sx[3 * tid + 1];
        float4 c = sx[3 * tid + 2];
        float4 p = sc[3 * tid + 0];
        float4 q = sc[3 * tid + 1];
        float4 r = sc[3 * tid + 2];

        float xv[12] = {a.x, a.y, a.z, a.w, b.x, b.y, b.z, b.w, c.x, c.y, c.z, c.w};
        float cv[12] = {p.x, p.y, p.z, p.w, q.x, q.y, q.z, q.w, r.x, r.y, r.z, r.w};
        float ov[12];

        #pragma unroll
        for (int pt = 0; pt < 4; ++pt) {
            float dx = xv[3 * pt + 0] - cv[3 * pt + 0];
            float dy = xv[3 * pt + 1] - cv[3 * pt + 1];
            float dz = xv[3 * pt + 2] - cv[3 * pt + 2];
            float n2 = fmaf(dx, dx, fmaf(dy, dy, dz * dz));
            // scale = min(1, R / max(n, 1e-12)) == min(1, R * rsqrt(max(n2, 1e-24)))
            float s = fminf(1.0f, RADIUS_F * rsqrtf(fmaxf(n2, 1e-24f)));
            ov[3 * pt + 0] = fmaf(dx, s, cv[3 * pt + 0]);
            ov[3 * pt + 1] = fmaf(dy, s, cv[3 * pt + 1]);
            ov[3 * pt + 2] = fmaf(dz, s, cv[3 * pt + 2]);
        }

        so[3 * tid + 0] = make_float4(ov[0], ov[1], ov[2],  ov[3]);
        so[3 * tid + 1] = make_float4(ov[4], ov[5], ov[6],  ov[7]);
        so[3 * tid + 2] = make_float4(ov[8], ov[9], ov[10], ov[11]);
    }
    __syncthreads();

    // ---- Phase 3: fully-coalesced smem -> global
    #pragma unroll
    for (int k = 0; k < 3; ++k) {
        o4[blockBase + k * THREADS + tid] = so[k * THREADS + tid];
    }
}

// Scalar tail for points not covered by full blocks (0 for the benched shape).
__global__ void circle_proj_tail(const float* __restrict__ x,
                                 const float* __restrict__ c,
                                 float* __restrict__ o,
                                 int start_pt, int n_pt)
{
    int p = start_pt + blockIdx.x * blockDim.x + threadIdx.x;
    if (p >= n_pt) return;
    float dx = x[3 * p + 0] - c[3 * p + 0];
    float dy = x[3 * p + 1] - c[3 * p + 1];
    float dz = x[3 * p + 2] - c[3 * p + 2];
    float n2 = fmaf(dx, dx, fmaf(dy, dy, dz * dz));
    float s = fminf(1.0f, RADIUS_F * rsqrtf(fmaxf(n2, 1e-24f)));
    o[3 * p + 0] = fmaf(dx, s, c[3 * p + 0]);
    o[3 * p + 1] = fmaf(dy, s, c[3 * p + 1]);
    o[3 * p + 2] = fmaf(dz, s, c[3 * p + 2]);
}

extern "C" void kernel_launch(void* const* d_in, const int* in_sizes, int n_in,
                              void* d_out, int out_size)
{
    const float* x = (const float*)d_in[0];
    const float* c = (const float*)d_in[1];
    float* o = (float*)d_out;

    int total_floats = in_sizes[0];          // B * 3
    int n_pts = total_floats / 3;
    int full_blocks = n_pts / PTS_PER_BLOCK; // 8192 for B = 8388608

    if (full_blocks > 0) {
        circle_proj_kernel<<<full_blocks, THREADS>>>(
            (const float4*)x, (const float4*)c, (float4*)o);
    }

    int done_pts = full_blocks * PTS_PER_BLOCK;
    int rem = n_pts - done_pts;
    if (rem > 0) {
        circle_proj_tail<<<(rem + 255) / 256, 256>>>(x, c, o, done_pts, n_pts);
    }
}

// round 5
// speedup vs baseline: 1.0810x; 1.0679x over previous
#include <cuda_runtime.h>

// CircleProjectionLayer: out = center + (x - center) * min(1, R / max(||x-center||, 1e-12))
// R = 1.0, B = 8388608 points, AoS float32 [B,3]. Pure HBM-streaming kernel.
//
// R4: R1's exact memory pattern (4 pts/thread, 3x LDG.128 per array, default
// caching — measured 6.96 TB/s effective) + single-wave persistent grid-stride
// loop (152 SMs x 8 CTAs) to remove wave-transition overhead and overlap
// iteration i stores with iteration i+1 loads.

#define RADIUS_F 1.0f
#define THREADS 256
#define PERSISTENT_BLOCKS (152 * 8)   // one full wave at occ=8 (32 regs, 256 thr)

__global__ __launch_bounds__(THREADS)
void circle_proj_kernel(const float4* __restrict__ x4,
                        const float4* __restrict__ c4,
                        float4* __restrict__ o4,
                        int n_groups)   // n_groups = B/4 ; each group = 3 float4
{
    const long stride = (long)gridDim.x * blockDim.x;

    for (long i = (long)blockIdx.x * blockDim.x + threadIdx.x;
         i < n_groups; i += stride) {

        long base = 3L * i;

        float4 xa = x4[base + 0];
        float4 xb = x4[base + 1];
        float4 xc = x4[base + 2];
        float4 ca = c4[base + 0];
        float4 cb = c4[base + 1];
        float4 cc = c4[base + 2];

        float xv[12] = {xa.x, xa.y, xa.z, xa.w, xb.x, xb.y, xb.z, xb.w, xc.x, xc.y, xc.z, xc.w};
        float cv[12] = {ca.x, ca.y, ca.z, ca.w, cb.x, cb.y, cb.z, cb.w, cc.x, cc.y, cc.z, cc.w};
        float ov[12];

        #pragma unroll
        for (int p = 0; p < 4; ++p) {
            float dx = xv[3*p + 0] - cv[3*p + 0];
            float dy = xv[3*p + 1] - cv[3*p + 1];
            float dz = xv[3*p + 2] - cv[3*p + 2];
            float n2 = fmaf(dx, dx, fmaf(dy, dy, dz * dz));
            // scale = min(1, R / max(n, 1e-12)) == min(1, R * rsqrt(max(n2, 1e-24)))
            float s = fminf(1.0f, RADIUS_F * rsqrtf(fmaxf(n2, 1e-24f)));
            ov[3*p + 0] = fmaf(dx, s, cv[3*p + 0]);
            ov[3*p + 1] = fmaf(dy, s, cv[3*p + 1]);
            ov[3*p + 2] = fmaf(dz, s, cv[3*p + 2]);
        }

        o4[base + 0] = make_float4(ov[0], ov[1], ov[2],  ov[3]);
        o4[base + 1] = make_float4(ov[4], ov[5], ov[6],  ov[7]);
        o4[base + 2] = make_float4(ov[8], ov[9], ov[10], ov[11]);
    }
}

// Scalar tail kernel for any leftover points (B not divisible by 4). For the
// benched shape (B = 8388608) this launches 0 blocks.
__global__ void circle_proj_tail(const float* __restrict__ x,
                                 const float* __restrict__ c,
                                 float* __restrict__ o,
                                 int start_pt, int n_pt)
{
    int p = start_pt + blockIdx.x * blockDim.x + threadIdx.x;
    if (p >= n_pt) return;
    float dx = x[3*p + 0] - c[3*p + 0];
    float dy = x[3*p + 1] - c[3*p + 1];
    float dz = x[3*p + 2] - c[3*p + 2];
    float n2 = fmaf(dx, dx, fmaf(dy, dy, dz * dz));
    float s = fminf(1.0f, RADIUS_F * rsqrtf(fmaxf(n2, 1e-24f)));
    o[3*p + 0] = fmaf(dx, s, c[3*p + 0]);
    o[3*p + 1] = fmaf(dy, s, c[3*p + 1]);
    o[3*p + 2] = fmaf(dz, s, c[3*p + 2]);
}

extern "C" void kernel_launch(void* const* d_in, const int* in_sizes, int n_in,
                              void* d_out, int out_size)
{
    const float* x = (const float*)d_in[0];
    const float* c = (const float*)d_in[1];
    float* o = (float*)d_out;

    int total_floats = in_sizes[0];      // B * 3
    int n_pts = total_floats / 3;
    int n_groups = n_pts / 4;            // 4 points per thread-iteration

    if (n_groups > 0) {
        int needed = (n_groups + THREADS - 1) / THREADS;
        int blocks = needed < PERSISTENT_BLOCKS ? needed : PERSISTENT_BLOCKS;
        circle_proj_kernel<<<blocks, THREADS>>>(
            (const float4*)x, (const float4*)c, (float4*)o, n_groups);
    }

    int done_pts = n_groups * 4;
    int rem = n_pts - done_pts;
    if (rem > 0) {
        circle_proj_tail<<<(rem + 255) / 256, 256>>>(x, c, o, done_pts, n_pts);
    }
}

// round 6
// speedup vs baseline: 1.1648x; 1.0776x over previous
#include <cuda_runtime.h>

// CircleProjectionLayer: out = center + (x - center) * min(1, R / max(||x-center||, 1e-12))
// R = 1.0, B = 8388608 points, AoS float32 [B,3]. Pure HBM-streaming kernel.
//
// R5: R1's winning structure (4 pts/thread, one CTA per contiguous tile,
// default caching — measured best at 43.4us kernel), with micro-cleanups only:
//  - 32-bit addressing (offsets < 2^27, no 64-bit IMAD pairs)
//  - __launch_bounds__(256, 8) to pin regs <= 32 (full occupancy)
//  - x/c load streams interleaved in issue order

#define RADIUS_F 1.0f
#define THREADS 256

__global__ __launch_bounds__(THREADS, 8)
void circle_proj_kernel(const float4* __restrict__ x4,
                        const float4* __restrict__ c4,
                        float4* __restrict__ o4,
                        int n_groups)   // n_groups = B/4 ; each group = 3 float4
{
    int i = blockIdx.x * THREADS + threadIdx.x;
    if (i >= n_groups) return;

    int base = 3 * i;   // max 3 * 2^21 * 16B = 100MB byte offset: fits 32-bit

    float4 xa = x4[base + 0];
    float4 ca = c4[base + 0];
    float4 xb = x4[base + 1];
    float4 cb = c4[base + 1];
    float4 xc = x4[base + 2];
    float4 cc = c4[base + 2];

    float xv[12] = {xa.x, xa.y, xa.z, xa.w, xb.x, xb.y, xb.z, xb.w, xc.x, xc.y, xc.z, xc.w};
    float cv[12] = {ca.x, ca.y, ca.z, ca.w, cb.x, cb.y, cb.z, cb.w, cc.x, cc.y, cc.z, cc.w};
    float ov[12];

    #pragma unroll
    for (int p = 0; p < 4; ++p) {
        float dx = xv[3*p + 0] - cv[3*p + 0];
        float dy = xv[3*p + 1] - cv[3*p + 1];
        float dz = xv[3*p + 2] - cv[3*p + 2];
        float n2 = fmaf(dx, dx, fmaf(dy, dy, dz * dz));
        // scale = min(1, R / max(n, 1e-12)) == min(1, R * rsqrt(max(n2, 1e-24)))
        float s = fminf(1.0f, RADIUS_F * rsqrtf(fmaxf(n2, 1e-24f)));
        ov[3*p + 0] = fmaf(dx, s, cv[3*p + 0]);
        ov[3*p + 1] = fmaf(dy, s, cv[3*p + 1]);
        ov[3*p + 2] = fmaf(dz, s, cv[3*p + 2]);
    }

    o4[base + 0] = make_float4(ov[0], ov[1], ov[2],  ov[3]);
    o4[base + 1] = make_float4(ov[4], ov[5], ov[6],  ov[7]);
    o4[base + 2] = make_float4(ov[8], ov[9], ov[10], ov[11]);
}

// Scalar tail kernel for any leftover points (B not divisible by 4). For the
// benched shape (B = 8388608) this launches 0 blocks.
__global__ void circle_proj_tail(const float* __restrict__ x,
                                 const float* __restrict__ c,
                                 float* __restrict__ o,
                                 int start_pt, int n_pt)
{
    int p = start_pt + blockIdx.x * blockDim.x + threadIdx.x;
    if (p >= n_pt) return;
    float dx = x[3*p + 0] - c[3*p + 0];
    float dy = x[3*p + 1] - c[3*p + 1];
    float dz = x[3*p + 2] - c[3*p + 2];
    float n2 = fmaf(dx, dx, fmaf(dy, dy, dz * dz));
    float s = fminf(1.0f, RADIUS_F * rsqrtf(fmaxf(n2, 1e-24f)));
    o[3*p + 0] = fmaf(dx, s, c[3*p + 0]);
    o[3*p + 1] = fmaf(dy, s, c[3*p + 1]);
    o[3*p + 2] = fmaf(dz, s, c[3*p + 2]);
}

extern "C" void kernel_launch(void* const* d_in, const int* in_sizes, int n_in,
                              void* d_out, int out_size)
{
    const float* x = (const float*)d_in[0];
    const float* c = (const float*)d_in[1];
    float* o = (float*)d_out;

    int total_floats = in_sizes[0];      // B * 3
    int n_pts = total_floats / 3;
    int n_groups = n_pts / 4;            // 4 points per thread

    if (n_groups > 0) {
        int blocks = (n_groups + THREADS - 1) / THREADS;
        circle_proj_kernel<<<blocks, THREADS>>>(
            (const float4*)x, (const float4*)c, (float4*)o, n_groups);
    }

    int done_pts = n_groups * 4;
    int rem = n_pts - done_pts;
    if (rem > 0) {
        circle_proj_tail<<<(rem + 255) / 256, 256>>>(x, c, o, done_pts, n_pts);
    }
}